// round 13
// baseline (speedup 1.0000x reference)
#include <cuda_runtime.h>

#define R_BINS 64
#define Z_BINS 64
#define NBINS  (R_BINS * Z_BINS)
#define HSTRIDE 65                       // pad: bank = (bi + bj) % 32
#define GRID_CTAS (148 * 6)              // 6 CTAs/SM co-resident
#define NTHREADS 256

#define PI_F     3.14159265358979f
#define INV_DR   6.4f                    // 1/0.15625
#define DR_F     0.15625f
#define DZ_F     0.0625f

__device__ unsigned int g_c1 = 0;        // zeroing-done arrivals (reaches 16)
__device__ unsigned int g_c2 = 0;        // flush-done arrivals (reaches grid)

__device__ __forceinline__ void accum_point(float x, float y, float z, float m,
                                            float* __restrict__ h) {
    float r  = sqrtf(fmaf(x, x, y * y));
    int   bi = (int)(r * INV_DR);                 // r >= 0 -> trunc == floor
    float fj = floorf((z + 2.0f) * 16.0f);
    int   bj = (int)fj;
    if (bi < R_BINS && (unsigned)bj < Z_BINS) {
        atomicAdd(&h[bi * HSTRIDE + bj], m);
    }
}

__global__ void __launch_bounds__(NTHREADS, 6)
fused_hist_kernel(const float* __restrict__ pos,    // (N,3) f32 flat
                  const float* __restrict__ mass,   // (N,)  f32
                  float* __restrict__ out,
                  int n)                            // N
{
    __shared__ float sh[2][R_BINS * HSTRIDE];

    const int tid  = threadIdx.x;
    const int wid  = tid >> 5;
    const int lane = tid & 31;

    // ---- Phase 0: CTAs 0..15 zero d_out (re-zeroed every graph replay)
    if (blockIdx.x < 16) {
        out[blockIdx.x * NTHREADS + tid] = 0.0f;
        __threadfence();
        __syncthreads();
        if (tid == 0) atomicAdd(&g_c1, 1u);
    }

    // ---- Phase 1: private histograms (2 sub-hists by warp parity)
    float* hist = sh[wid & 1];
    for (int i = tid; i < 2 * R_BINS * HSTRIDE; i += NTHREADS)
        (&sh[0][0])[i] = 0.0f;
    __syncthreads();

    // Warp-granular grid stride: each warp owns 256-point blocks.
    // Lane l handles points blockBase + 32k + l  (12B lane stride -> coalesced
    // scalar loads: 3 wavefronts per x/y/z LDG, 1 per mass LDG).
    const int gw = blockIdx.x * (NTHREADS / 32) + wid;
    const int nw = gridDim.x * (NTHREADS / 32);

    for (int base = gw * 256; base < n; base += nw * 256) {
        #pragma unroll 1
        for (int half = 0; half < 2; half++) {
            const int p0 = base + half * 128 + lane;
            float x[4], y[4], z[4], m[4];
            #pragma unroll
            for (int k = 0; k < 4; k++) {
                int p = p0 + 32 * k;
                x[k] = pos[3 * p + 0];
                y[k] = pos[3 * p + 1];
                z[k] = pos[3 * p + 2];
                m[k] = mass[p];
            }
            #pragma unroll
            for (int k = 0; k < 4; k++)
                accum_point(x[k], y[k], z[k], m[k], hist);
        }
    }
    __syncthreads();

    // ---- Phase 2: wait until d_out is zeroed (condition set at kernel start
    // by CTAs 0..15, so later waves can never deadlock here)
    if (tid == 0) {
        while (atomicAdd(&g_c1, 0u) < 16u) { __nanosleep(64); }
    }
    __syncthreads();
    __threadfence();

    // ---- Phase 3: flush, pre-scaled by 1/volume (normalize folded in)
    for (int i = tid; i < NBINS; i += NTHREADS) {
        int row = i >> 6;
        int col = i & 63;
        float v = sh[0][row * HSTRIDE + col] + sh[1][row * HSTRIDE + col];
        if (v != 0.0f) {
            float r0  = (float)row * DR_F;
            float r1  = (float)(row + 1) * DR_F;
            float vol = PI_F * (r1 * r1 - r0 * r0) * DZ_F;
            atomicAdd(&out[i], v / vol);
        }
    }

    // ---- Phase 4: last CTA resets counters (deterministic across replays)
    __threadfence();
    __syncthreads();
    if (tid == 0) {
        unsigned int v = atomicAdd(&g_c2, 1u);
        if (v == gridDim.x - 1) {
            atomicExch(&g_c1, 0u);
            atomicExch(&g_c2, 0u);
        }
    }
}

extern "C" void kernel_launch(void* const* d_in, const int* in_sizes, int n_in,
                              void* d_out, int out_size) {
    const float* pos  = (const float*)d_in[0];   // positions (N,3) f32
    const float* mass = (const float*)d_in[1];   // masses (N,) f32
    float* out = (float*)d_out;

    int n = in_sizes[1];     // N = 2^24

    fused_hist_kernel<<<GRID_CTAS, NTHREADS>>>(pos, mass, out, n);
}

// round 14
// speedup vs baseline: 1.1685x; 1.1685x over previous
#include <cuda_runtime.h>

#define R_BINS 64
#define Z_BINS 64
#define NBINS  (R_BINS * Z_BINS)
#define HSTRIDE 65                       // pad: bank = (bi + bj) % 32
#define GRID_CTAS (148 * 4)              // 4 CTAs/SM co-resident
#define NTHREADS 256
#define WARPS_PER_CTA (NTHREADS / 32)

#define PI_F     3.14159265358979f
#define INV_DR   6.4f                    // 1/0.15625
#define DR_F     0.15625f
#define DZ_F     0.0625f

__device__ unsigned int g_c1 = 0;        // zeroing-done arrivals (reaches 16)
__device__ unsigned int g_c2 = 0;        // flush-done arrivals (reaches grid)

__device__ __forceinline__ void accum_point(float x, float y, float z, float m,
                                            float* __restrict__ h) {
    float r  = sqrtf(fmaf(x, x, y * y));
    int   bi = (int)(r * INV_DR);                 // r >= 0 -> trunc == floor
    float fj = floorf((z + 2.0f) * 16.0f);
    int   bj = (int)fj;
    if (bi < R_BINS && (unsigned)bj < Z_BINS) {
        atomicAdd(&h[bi * HSTRIDE + bj], m);
    }
}

// Load 4 points (lane-strided by 32) with OOB clamp. 16 independent LDGs.
__device__ __forceinline__ void load_batch(const float* __restrict__ pos,
                                           const float* __restrict__ mass,
                                           int n, int p0,
                                           float* x, float* y, float* z, float* m) {
    #pragma unroll
    for (int k = 0; k < 4; k++) {
        int  p = p0 + 32 * k;
        bool v = p < n;
        int  q = v ? p : (n - 1);
        x[k] = pos[3 * q + 0];
        y[k] = pos[3 * q + 1];
        z[k] = pos[3 * q + 2];
        m[k] = v ? mass[q] : 0.0f;
    }
}

__global__ void __launch_bounds__(NTHREADS, 4)
fused_hist_kernel(const float* __restrict__ pos,    // (N,3) f32 flat
                  const float* __restrict__ mass,   // (N,)  f32
                  float* __restrict__ out,
                  int n)                            // N
{
    __shared__ float sh[2][R_BINS * HSTRIDE];

    const int tid  = threadIdx.x;
    const int wid  = tid >> 5;
    const int lane = tid & 31;

    // ---- Phase 0: CTAs 0..15 zero d_out (re-zeroed every graph replay)
    if (blockIdx.x < 16) {
        out[blockIdx.x * NTHREADS + tid] = 0.0f;
        __threadfence();
        __syncthreads();
        if (tid == 0) atomicAdd(&g_c1, 1u);
    }

    // ---- Phase 1: private histograms (2 sub-hists by warp parity)
    float* hist = sh[wid & 1];
    for (int i = tid; i < 2 * R_BINS * HSTRIDE; i += NTHREADS)
        (&sh[0][0])[i] = 0.0f;
    __syncthreads();

    // Warp-granular grid stride, 128 points per warp-iter (4/lane, 32-strided).
    // Software pipeline: batch t+1's 16 LDGs issued before processing batch t.
    const int gw   = blockIdx.x * WARPS_PER_CTA + wid;
    const int nw   = gridDim.x * WARPS_PER_CTA;
    const int step = nw * 128;

    int base = gw * 128 + lane;
    if (base < n + lane) {  // every warp has at least one (possibly clamped) batch
        float xa[4], ya[4], za[4], ma[4];
        load_batch(pos, mass, n, base, xa, ya, za, ma);

        for (base += step; base - lane < n; base += step) {
            float xb[4], yb[4], zb[4], mb[4];
            load_batch(pos, mass, n, base, xb, yb, zb, mb);   // in flight...

            #pragma unroll
            for (int k = 0; k < 4; k++)
                accum_point(xa[k], ya[k], za[k], ma[k], hist); // ...while we work

            #pragma unroll
            for (int k = 0; k < 4; k++) {
                xa[k] = xb[k]; ya[k] = yb[k]; za[k] = zb[k]; ma[k] = mb[k];
            }
        }
        #pragma unroll
        for (int k = 0; k < 4; k++)
            accum_point(xa[k], ya[k], za[k], ma[k], hist);
    }
    __syncthreads();

    // ---- Phase 2: wait until d_out is zeroed (flag set at kernel start by
    // first-wave CTAs 0..15, so no deadlock)
    if (tid == 0) {
        while (atomicAdd(&g_c1, 0u) < 16u) { __nanosleep(64); }
    }
    __syncthreads();
    __threadfence();

    // ---- Phase 3: flush, pre-scaled by 1/volume (normalize folded in)
    for (int i = tid; i < NBINS; i += NTHREADS) {
        int row = i >> 6;
        int col = i & 63;
        float v = sh[0][row * HSTRIDE + col] + sh[1][row * HSTRIDE + col];
        if (v != 0.0f) {
            float r0  = (float)row * DR_F;
            float r1  = (float)(row + 1) * DR_F;
            float vol = PI_F * (r1 * r1 - r0 * r0) * DZ_F;
            atomicAdd(&out[i], v / vol);
        }
    }

    // ---- Phase 4: last CTA resets counters (deterministic across replays)
    __threadfence();
    __syncthreads();
    if (tid == 0) {
        unsigned int v = atomicAdd(&g_c2, 1u);
        if (v == gridDim.x - 1) {
            atomicExch(&g_c1, 0u);
            atomicExch(&g_c2, 0u);
        }
    }
}

extern "C" void kernel_launch(void* const* d_in, const int* in_sizes, int n_in,
                              void* d_out, int out_size) {
    const float* pos  = (const float*)d_in[0];   // positions (N,3) f32
    const float* mass = (const float*)d_in[1];   // masses (N,) f32
    float* out = (float*)d_out;

    int n = in_sizes[1];     // N = 2^24

    fused_hist_kernel<<<GRID_CTAS, NTHREADS>>>(pos, mass, out, n);
}